// round 2
// baseline (speedup 1.0000x reference)
#include <cuda_runtime.h>

// SSIM loss, fused separable tiled kernel with immediate-form Gaussian taps.
// pred/target: (16,3,512,512) f32; window input ignored (deterministic
// sigma=1.5, size=11 separable Gaussian, taps baked as immediates so FFMA
// uses the rt=1 imm form and no smem broadcast loads are needed).

#define RAD 5
#define TX 32
#define TY 32
#define PH (TY + 2 * RAD)   // 42 rows incl. halo
#define PW (TX + 2 * RAD)   // 42 cols incl. halo
#define SPITCH 44           // sp/st row pitch (floats): 16B-aligned, conflict-free
#define IMG 512
#define NIMG 48             // 16 batch * 3 chan
#define TILES_X 16
#define TILES_Y 16
#define NBLK (TILES_X * TILES_Y * NIMG)   // 12288
#define SSIM_C1 1.0e-4f
#define SSIM_C2 9.0e-4f

__device__ float g_bsum[NBLK];

__global__ __launch_bounds__(128, 4)
void ssim_main(const float* __restrict__ pred, const float* __restrict__ target)
{
    // Normalized 1-D Gaussian, sigma=1.5, k=11 (exact to ~1e-7).
    constexpr float GW[11] = {
        0.00102838f, 0.00759876f, 0.03600077f, 0.10936069f, 0.21300553f,
        0.26601173f,
        0.21300553f, 0.10936069f, 0.03600077f, 0.00759876f, 0.00102838f
    };

    __shared__ __align__(16) float sp[PH][SPITCH];
    __shared__ __align__(16) float st[PH][SPITCH];
    __shared__ __align__(16) float hb[5][PH][TX];
    __shared__ float wsum[4];

    const int tid  = threadIdx.x;
    const int lane = tid & 31;
    const int wrp  = tid >> 5;

    const int tile_x = blockIdx.x & (TILES_X - 1);
    const int tile_y = blockIdx.x >> 4;
    const int img    = blockIdx.y;
    const float* pb = pred   + (size_t)img * IMG * IMG;
    const float* tb = target + (size_t)img * IMG * IMG;
    const int x0 = tile_x * TX - RAD;
    const int y0 = tile_y * TY - RAD;

    // ---- Phase 1: load 42x42 halo (zero-padded) -------------------------
    #pragma unroll 1
    for (int r = wrp; r < PH; r += 4) {
        const int gy = y0 + r;
        const bool rok = ((unsigned)gy < (unsigned)IMG);
        const float* prow = pb + gy * IMG;
        const float* trow = tb + gy * IMG;
        {
            const int gx = x0 + lane;
            const bool ok = rok && ((unsigned)gx < (unsigned)IMG);
            sp[r][lane] = ok ? __ldg(prow + gx) : 0.f;
            st[r][lane] = ok ? __ldg(trow + gx) : 0.f;
        }
        if (lane < PW - 32) {
            const int gx = x0 + lane + 32;
            const bool ok = rok && ((unsigned)gx < (unsigned)IMG);
            sp[r][lane + 32] = ok ? __ldg(prow + gx) : 0.f;
            st[r][lane + 32] = ok ? __ldg(trow + gx) : 0.f;
        }
    }
    __syncthreads();

    // ---- Phase 2: horizontal blur, 4 outputs/thread, vector LDS/STS -----
    // items: 42 rows x 8 col-groups of 4
    #pragma unroll 1
    for (int it = tid; it < PH * 8; it += 128) {
        const int r  = it >> 3;
        const int cx = (it & 7) << 2;

        float p[16], t[16];
        #pragma unroll
        for (int u = 0; u < 4; u++) {
            const float4 Pv = *reinterpret_cast<const float4*>(&sp[r][cx + 4 * u]);
            const float4 Tv = *reinterpret_cast<const float4*>(&st[r][cx + 4 * u]);
            p[4 * u + 0] = Pv.x; p[4 * u + 1] = Pv.y; p[4 * u + 2] = Pv.z; p[4 * u + 3] = Pv.w;
            t[4 * u + 0] = Tv.x; t[4 * u + 1] = Tv.y; t[4 * u + 2] = Tv.z; t[4 * u + 3] = Tv.w;
        }

        float pp[14], tt[14], pt[14];
        #pragma unroll
        for (int i = 0; i < 14; i++) {
            pp[i] = p[i] * p[i];
            tt[i] = t[i] * t[i];
            pt[i] = p[i] * t[i];
        }

        float s1[4] = {0.f, 0.f, 0.f, 0.f};
        float s2[4] = {0.f, 0.f, 0.f, 0.f};
        float s3[4] = {0.f, 0.f, 0.f, 0.f};
        float s4[4] = {0.f, 0.f, 0.f, 0.f};
        float s5[4] = {0.f, 0.f, 0.f, 0.f};
        #pragma unroll
        for (int k = 0; k < 11; k++) {
            #pragma unroll
            for (int j = 0; j < 4; j++) {
                s1[j] = fmaf(GW[k], p[j + k],  s1[j]);
                s2[j] = fmaf(GW[k], t[j + k],  s2[j]);
                s3[j] = fmaf(GW[k], pp[j + k], s3[j]);
                s4[j] = fmaf(GW[k], tt[j + k], s4[j]);
                s5[j] = fmaf(GW[k], pt[j + k], s5[j]);
            }
        }

        *reinterpret_cast<float4*>(&hb[0][r][cx]) = make_float4(s1[0], s1[1], s1[2], s1[3]);
        *reinterpret_cast<float4*>(&hb[1][r][cx]) = make_float4(s2[0], s2[1], s2[2], s2[3]);
        *reinterpret_cast<float4*>(&hb[2][r][cx]) = make_float4(s3[0], s3[1], s3[2], s3[3]);
        *reinterpret_cast<float4*>(&hb[3][r][cx]) = make_float4(s4[0], s4[1], s4[2], s4[3]);
        *reinterpret_cast<float4*>(&hb[4][r][cx]) = make_float4(s5[0], s5[1], s5[2], s5[3]);
    }
    __syncthreads();

    // ---- Phase 3: vertical blur (8 rows/thread) + SSIM ------------------
    const int c  = lane;
    const int yb = wrp * 8;

    float m1[8], m2[8], m3[8], m4[8], m5[8];
    #pragma unroll
    for (int j = 0; j < 8; j++) { m1[j] = 0.f; m2[j] = 0.f; m3[j] = 0.f; m4[j] = 0.f; m5[j] = 0.f; }

    #pragma unroll
    for (int k = 0; k < 18; k++) {
        const float a1 = hb[0][yb + k][c];
        const float a2 = hb[1][yb + k][c];
        const float a3 = hb[2][yb + k][c];
        const float a4 = hb[3][yb + k][c];
        const float a5 = hb[4][yb + k][c];
        #pragma unroll
        for (int j = 0; j < 8; j++) {
            if (k - j >= 0 && k - j < 11) {
                m1[j] = fmaf(GW[k - j], a1, m1[j]);
                m2[j] = fmaf(GW[k - j], a2, m2[j]);
                m3[j] = fmaf(GW[k - j], a3, m3[j]);
                m4[j] = fmaf(GW[k - j], a4, m4[j]);
                m5[j] = fmaf(GW[k - j], a5, m5[j]);
            }
        }
    }

    float num[8], den[8];
    #pragma unroll
    for (int j = 0; j < 8; j++) {
        const float mu1sq = m1[j] * m1[j];
        const float mu2sq = m2[j] * m2[j];
        const float mu12  = m1[j] * m2[j];
        const float v1    = m3[j] - mu1sq;   // sigma1_sq
        const float v2    = m4[j] - mu2sq;   // sigma2_sq
        const float v12   = m5[j] - mu12;    // sigma12
        num[j] = fmaf(2.f, mu12, SSIM_C1) * fmaf(2.f, v12, SSIM_C2);
        den[j] = (mu1sq + mu2sq + SSIM_C1) * (v1 + v2 + SSIM_C2);
    }

    // Combine 4 quotients per division (den >= 9e-8 each; 4-way product
    // >= 6.6e-29, stays normal in fp32).
    float ssum = 0.f;
    #pragma unroll
    for (int h = 0; h < 2; h++) {
        const int b = 4 * h;
        const float n01 = fmaf(num[b + 0], den[b + 1], num[b + 1] * den[b + 0]);
        const float d01 = den[b + 0] * den[b + 1];
        const float n23 = fmaf(num[b + 2], den[b + 3], num[b + 3] * den[b + 2]);
        const float d23 = den[b + 2] * den[b + 3];
        const float nall = fmaf(n01, d23, n23 * d01);
        const float dall = d01 * d23;
        ssum += __fdividef(nall, dall);
    }

    // ---- Block reduction -> per-block sum (no atomics, no zero pass) ----
    #pragma unroll
    for (int o = 16; o > 0; o >>= 1)
        ssum += __shfl_xor_sync(0xffffffffu, ssum, o);
    if (lane == 0) wsum[wrp] = ssum;
    __syncthreads();
    if (tid == 0) {
        const float bs = wsum[0] + wsum[1] + wsum[2] + wsum[3];
        g_bsum[blockIdx.y * (TILES_X * TILES_Y) + blockIdx.x] = bs;
    }
}

__global__ __launch_bounds__(256)
void ssim_reduce(float* __restrict__ out)
{
    __shared__ double ws[8];
    const int tid = threadIdx.x;

    float s = 0.f;
    #pragma unroll 1
    for (int i = tid; i < NBLK; i += 256) s += g_bsum[i];

    double d = (double)s;
    #pragma unroll
    for (int o = 16; o > 0; o >>= 1)
        d += __shfl_xor_sync(0xffffffffu, d, o);
    if ((tid & 31) == 0) ws[tid >> 5] = d;
    __syncthreads();
    if (tid == 0) {
        double tot = 0.0;
        #pragma unroll
        for (int i = 0; i < 8; i++) tot += ws[i];
        const double n = 12582912.0;  // 16*3*512*512
        out[0] = (float)(1.0 - tot / n);
    }
}

extern "C" void kernel_launch(void* const* d_in, const int* in_sizes, int n_in,
                              void* d_out, int out_size)
{
    const float* pred   = (const float*)d_in[0];
    const float* target = (const float*)d_in[1];
    (void)in_sizes; (void)n_in; (void)out_size;

    dim3 grid(TILES_X * TILES_Y, NIMG);   // (256, 48)
    ssim_main<<<grid, 128>>>(pred, target);
    ssim_reduce<<<1, 256>>>((float*)d_out);
}

// round 3
// speedup vs baseline: 1.5460x; 1.5460x over previous
#include <cuda_runtime.h>

// SSIM loss, single fused kernel, f32x2-packed separable blur.
// pred/target: (16,3,512,512) f32. Output: scalar f32 = 1 - mean(ssim_map).

#define RAD 5
#define TX 32
#define TY 32
#define PH 42               // TY + 2*RAD
#define PW 42               // TX + 2*RAD
#define HB_PITCH 34         // float2 pitch for hb12/hb34 (272B = 16 mod 128)
#define HB5_PITCH 36        // float pitch for hb5 (144B = 16 mod 128)
#define IMG 512
#define NIMG 48
#define TILES 256           // 16 x 16 tiles per image
#define NBLK (TILES * NIMG) // 12288
#define SSIM_C1 1.0e-4f
#define SSIM_C2 9.0e-4f

__device__ float g_bsum[NBLK];
__device__ int g_cnt;       // zero-initialized; last block resets to 0 each run

union F2U { float2 f; unsigned long long u; };

__device__ __forceinline__ unsigned long long pack2(float x, float y) {
    unsigned long long r;
    asm("mov.b64 %0, {%1, %2};" : "=l"(r) : "f"(x), "f"(y));
    return r;
}
__device__ __forceinline__ unsigned long long fma2(unsigned long long a,
                                                   unsigned long long b,
                                                   unsigned long long c) {
    unsigned long long d;
    asm("fma.rn.f32x2 %0, %1, %2, %3;" : "=l"(d) : "l"(a), "l"(b), "l"(c));
    return d;
}
__device__ __forceinline__ unsigned long long mul2(unsigned long long a,
                                                   unsigned long long b) {
    unsigned long long d;
    asm("mul.rn.f32x2 %0, %1, %2;" : "=l"(d) : "l"(a), "l"(b));
    return d;
}

__global__ __launch_bounds__(256)
void ssim_fused(const float* __restrict__ pred,
                const float* __restrict__ target,
                float* __restrict__ out)
{
    __shared__ float2 spt[PH][PW];          // (p,t) interleaved, pitch 42 f2
    __shared__ float2 hb12[PH][HB_PITCH];   // (h(p), h(t))
    __shared__ float2 hb34[PH][HB_PITCH];   // (h(p^2), h(t^2))
    __shared__ float  hb5[PH][HB5_PITCH];   // h(p*t)
    __shared__ float  wsum[4];
    __shared__ double dsum[8];
    __shared__ int    s_last;

    // Normalized 1-D Gaussian, sigma=1.5, size 11.
    const float GWs[11] = {
        0.00102838f, 0.00759876f, 0.03600077f, 0.10936069f, 0.21300553f,
        0.26601173f,
        0.21300553f, 0.10936069f, 0.03600077f, 0.00759876f, 0.00102838f
    };
    unsigned long long GWp[11];
    #pragma unroll
    for (int k = 0; k < 11; k++) GWp[k] = pack2(GWs[k], GWs[k]);
    const unsigned long long NEG1 = pack2(-1.0f, -1.0f);

    const int tid  = threadIdx.x;
    const int lane = tid & 31;
    const int wrp  = tid >> 5;

    const int tile_x = blockIdx.x & 15;
    const int tile_y = blockIdx.x >> 4;
    const int bid    = blockIdx.y * TILES + blockIdx.x;
    const float* pb = pred   + (size_t)blockIdx.y * IMG * IMG;
    const float* tb = target + (size_t)blockIdx.y * IMG * IMG;
    const int x0 = tile_x * TX - RAD;
    const int y0 = tile_y * TY - RAD;

    // ---- Phase 1: load 42x42 halo, interleave (p,t) ---------------------
    #pragma unroll 1
    for (int r = wrp; r < PH; r += 8) {
        const int gy = y0 + r;
        const bool rok = ((unsigned)gy < (unsigned)IMG);
        const float* prow = pb + gy * IMG;
        const float* trow = tb + gy * IMG;
        {
            const int gx = x0 + lane;
            const bool ok = rok && ((unsigned)gx < (unsigned)IMG);
            spt[r][lane] = make_float2(ok ? __ldg(prow + gx) : 0.f,
                                       ok ? __ldg(trow + gx) : 0.f);
        }
        if (lane < PW - 32) {
            const int gx = x0 + lane + 32;
            const bool ok = rok && ((unsigned)gx < (unsigned)IMG);
            spt[r][lane + 32] = make_float2(ok ? __ldg(prow + gx) : 0.f,
                                            ok ? __ldg(trow + gx) : 0.f);
        }
    }
    __syncthreads();

    // ---- Phase 2: horizontal blur, 4 output cols/thread, f32x2 packed ---
    // item = g*42 + r : column group g (cols 4g..4g+3), row r. 336 items.
    #pragma unroll
    for (int half = 0; half < 2; half++) {
        const int it = tid + half * 256;
        if (it < PH * 8) {
            const int g  = it / PH;
            const int r  = it - g * PH;
            const int cx = g * 4;

            float4 raw[7];
            const float4* rp = reinterpret_cast<const float4*>(&spt[r][cx]);
            #pragma unroll
            for (int q = 0; q < 7; q++) raw[q] = rp[q];

            F2U acc12[4], acc34[4];
            float acc5[4];
            #pragma unroll
            for (int j = 0; j < 4; j++) {
                acc12[j].f = make_float2(0.f, 0.f);
                acc34[j].f = make_float2(0.f, 0.f);
                acc5[j] = 0.f;
            }

            #pragma unroll
            for (int k = 0; k < 14; k++) {
                F2U e;
                e.f.x = (k & 1) ? raw[k >> 1].z : raw[k >> 1].x;
                e.f.y = (k & 1) ? raw[k >> 1].w : raw[k >> 1].y;
                F2U sq; sq.u = mul2(e.u, e.u);
                const float x = e.f.x * e.f.y;
                #pragma unroll
                for (int j = 0; j < 4; j++) {
                    const int w = k - j;
                    if (w >= 0 && w < 11) {
                        acc12[j].u = fma2(GWp[w], e.u,  acc12[j].u);
                        acc34[j].u = fma2(GWp[w], sq.u, acc34[j].u);
                        acc5[j]    = fmaf(GWs[w], x, acc5[j]);
                    }
                }
            }

            *reinterpret_cast<float4*>(&hb12[r][cx]) =
                make_float4(acc12[0].f.x, acc12[0].f.y, acc12[1].f.x, acc12[1].f.y);
            *reinterpret_cast<float4*>(&hb12[r][cx + 2]) =
                make_float4(acc12[2].f.x, acc12[2].f.y, acc12[3].f.x, acc12[3].f.y);
            *reinterpret_cast<float4*>(&hb34[r][cx]) =
                make_float4(acc34[0].f.x, acc34[0].f.y, acc34[1].f.x, acc34[1].f.y);
            *reinterpret_cast<float4*>(&hb34[r][cx + 2]) =
                make_float4(acc34[2].f.x, acc34[2].f.y, acc34[3].f.x, acc34[3].f.y);
            *reinterpret_cast<float4*>(&hb5[r][cx]) =
                make_float4(acc5[0], acc5[1], acc5[2], acc5[3]);
        }
    }
    __syncthreads();

    // ---- Phase 3: vertical blur (warps 0-3, 8 rows/thread) + SSIM -------
    if (wrp < 4) {
        const int c  = lane;
        const int yb = wrp * 8;

        F2U a12[8], a34[8];
        float a5[8];
        #pragma unroll
        for (int j = 0; j < 8; j++) {
            a12[j].f = make_float2(0.f, 0.f);
            a34[j].f = make_float2(0.f, 0.f);
            a5[j] = 0.f;
        }

        #pragma unroll
        for (int k = 0; k < 18; k++) {
            F2U h12; h12.f = hb12[yb + k][c];
            F2U h34; h34.f = hb34[yb + k][c];
            const float h5 = hb5[yb + k][c];
            #pragma unroll
            for (int j = 0; j < 8; j++) {
                const int w = k - j;
                if (w >= 0 && w < 11) {
                    a12[j].u = fma2(GWp[w], h12.u, a12[j].u);
                    a34[j].u = fma2(GWp[w], h34.u, a34[j].u);
                    a5[j]    = fmaf(GWs[w], h5, a5[j]);
                }
            }
        }

        float num[8], den[8];
        #pragma unroll
        for (int j = 0; j < 8; j++) {
            F2U musq; musq.u = mul2(a12[j].u, a12[j].u);        // (mu1^2, mu2^2)
            F2U sig;  sig.u  = fma2(NEG1, musq.u, a34[j].u);    // (sig1^2, sig2^2)
            const float mu12 = a12[j].f.x * a12[j].f.y;
            const float s12v = a5[j] - mu12;
            num[j] = fmaf(2.f, mu12, SSIM_C1) * fmaf(2.f, s12v, SSIM_C2);
            den[j] = (musq.f.x + musq.f.y + SSIM_C1) * (sig.f.x + sig.f.y + SSIM_C2);
        }

        // Combine 4 quotients per division (den >= ~9e-8; 4-way product
        // >= ~6.6e-29, stays normal in fp32).
        float ssum = 0.f;
        #pragma unroll
        for (int h = 0; h < 2; h++) {
            const int b = 4 * h;
            const float n01 = fmaf(num[b + 0], den[b + 1], num[b + 1] * den[b + 0]);
            const float d01 = den[b + 0] * den[b + 1];
            const float n23 = fmaf(num[b + 2], den[b + 3], num[b + 3] * den[b + 2]);
            const float d23 = den[b + 2] * den[b + 3];
            const float nall = fmaf(n01, d23, n23 * d01);
            const float dall = d01 * d23;
            ssum += __fdividef(nall, dall);
        }

        #pragma unroll
        for (int o = 16; o > 0; o >>= 1)
            ssum += __shfl_xor_sync(0xffffffffu, ssum, o);
        if (lane == 0) wsum[wrp] = ssum;
    }
    __syncthreads();

    // ---- Per-block sum + last-block-done global reduction ---------------
    if (tid == 0) {
        g_bsum[bid] = wsum[0] + wsum[1] + wsum[2] + wsum[3];
        __threadfence();
        const int old = atomicAdd(&g_cnt, 1);
        s_last = (old == NBLK - 1) ? 1 : 0;
    }
    __syncthreads();

    if (s_last) {
        __threadfence();
        double acc0 = 0.0, acc1 = 0.0, acc2 = 0.0, acc3 = 0.0;
        #pragma unroll 1
        for (int i = tid; i < NBLK; i += 1024) {   // 12 iterations, 4-way MLP
            acc0 += (double)g_bsum[i];
            acc1 += (double)g_bsum[i + 256];
            acc2 += (double)g_bsum[i + 512];
            acc3 += (double)g_bsum[i + 768];
        }
        double d = (acc0 + acc1) + (acc2 + acc3);
        #pragma unroll
        for (int o = 16; o > 0; o >>= 1)
            d += __shfl_xor_sync(0xffffffffu, d, o);
        if (lane == 0) dsum[wrp] = d;
        __syncthreads();
        if (tid == 0) {
            double tot = 0.0;
            #pragma unroll
            for (int i = 0; i < 8; i++) tot += dsum[i];
            out[0] = (float)(1.0 - tot / 12582912.0);   // 16*3*512*512
            g_cnt = 0;                                   // reset for next replay
        }
    }
}

extern "C" void kernel_launch(void* const* d_in, const int* in_sizes, int n_in,
                              void* d_out, int out_size)
{
    const float* pred   = (const float*)d_in[0];
    const float* target = (const float*)d_in[1];
    (void)in_sizes; (void)n_in; (void)out_size;

    dim3 grid(TILES, NIMG);   // (256, 48)
    ssim_fused<<<grid, 256>>>(pred, target, (float*)d_out);
}